// round 6
// baseline (speedup 1.0000x reference)
#include <cuda_runtime.h>
#include <cstdint>

// 3x3 stride-1 pad-1 conv, 1 channel, weight = w * outer(kx,kx), kx=[den,1,den].
// x: (16,1,2048,2048) fp32 -> out same shape.
// cp.async.bulk row copies (1 instr / 544B row) into smem via mbarrier:
// DMA-style fill = full-tile MLP with near-zero issue/ALU cost.

#define TCOLS 128
#define TROWS 32
#define SROWS 34            // TROWS + 2
#define PITCH 136           // halo(4-pad incl. left) + 128 + right halo; 544B, 16B-mult

__global__ __launch_bounds__(256)
void conv3x3_bulk(const float* __restrict__ x,
                  const float* __restrict__ w,
                  const float* __restrict__ den,
                  float* __restrict__ out,
                  int H, int W)
{
    __shared__ float tile[SROWS * PITCH];
    __shared__ uint64_t mbar;

    const int tid  = threadIdx.x;
    const int lane = tid & 31;
    const int wid  = tid >> 5;

    const int colbase = blockIdx.x * TCOLS;
    const int row0    = blockIdx.y * TROWS;
    const int b       = blockIdx.z;

    const size_t img = (size_t)H * W;
    const float* __restrict__ xb = x + (size_t)b * img;
    float*       __restrict__ ob = out + (size_t)b * img;

    const bool leftOK  = colbase > 0;
    const bool rightOK = (colbase + TCOLS) < W;

    // smem float f of row r <-> gmem col (colbase - 4 + f)
    // interior CTA : copy 544B from gx0 = colbase-4, dest off 0   -> smem[0..136)
    // bx == 0      : copy 528B from gx0 = 0,         dest off 16B -> smem[4..136) (smem[3] unwritten)
    // bx == last   : copy 528B from gx0 = colbase-4, dest off 0   -> smem[0..132) (smem[132..) unwritten)
    const int  src_gx   = leftOK ? (colbase - 4) : 0;
    const int  dst_off  = leftOK ? 0 : 16;                  // bytes
    const int  row_sz   = (leftOK && rightOK) ? 544 : 528;  // bytes
    const int  r_lo     = (row0 == 0) ? 1 : 0;              // first valid smem row
    const int  r_hi     = (row0 + TROWS >= H) ? 32 : 33;    // last valid smem row

    const uint32_t sbase = (uint32_t)__cvta_generic_to_shared(tile);
    const uint32_t maddr = (uint32_t)__cvta_generic_to_shared(&mbar);

    if (tid == 0) {
        asm volatile("mbarrier.init.shared.b64 [%0], 1;" :: "r"(maddr) : "memory");
    }
    // zero OOB rows (only edge-y CTAs take these)
    if (row0 == 0 && tid < PITCH)            tile[tid] = 0.0f;
    if (row0 + TROWS >= H && tid < PITCH)    tile[33 * PITCH + tid] = 0.0f;
    __syncthreads();

    if (tid == 0) {
        const uint32_t total = (uint32_t)(r_hi - r_lo + 1) * (uint32_t)row_sz;
        asm volatile("mbarrier.arrive.expect_tx.shared.b64 _, [%0], %1;"
                     :: "r"(maddr), "r"(total) : "memory");
        const float* src = xb + (size_t)(row0 - 1 + r_lo) * W + src_gx;
        uint32_t dst = sbase + (uint32_t)(r_lo * PITCH) * 4u + (uint32_t)dst_off;
        for (int r = r_lo; r <= r_hi; r++) {
            asm volatile("cp.async.bulk.shared::cta.global.mbarrier::complete_tx::bytes "
                         "[%0], [%1], %2, [%3];"
                         :: "r"(dst), "l"(src), "r"(row_sz), "r"(maddr) : "memory");
            src += W;
            dst += PITCH * 4u;
        }
    }

    // effective 3x3 weights (overlaps with DMA)
    const float d = den[0];
    const float kv[3] = {d, 1.0f, d};
    float k[9];
    #pragma unroll
    for (int i = 0; i < 3; i++)
        #pragma unroll
        for (int j = 0; j < 3; j++)
            k[i * 3 + j] = __ldg(&w[i * 3 + j]) * kv[i] * kv[j];

    // wait for tile (parity 0 every launch: barrier is re-inited per launch)
    {
        uint32_t done;
        asm volatile(
            "{\n\t.reg .pred p;\n\t"
            "mbarrier.try_wait.parity.shared.b64 p, [%1], 0;\n\t"
            "selp.b32 %0, 1, 0, p;\n\t}"
            : "=r"(done) : "r"(maddr) : "memory");
        while (!done) {
            asm volatile(
                "{\n\t.reg .pred p;\n\t"
                "mbarrier.try_wait.parity.shared.b64 p, [%1], 0;\n\t"
                "selp.b32 %0, 1, 0, p;\n\t}"
                : "=r"(done) : "r"(maddr) : "memory");
        }
    }
    __syncthreads();

    // ---------------- compute: warp wid -> output rows [4w, 4w+4) ----------------
    const int base_f = 4 * lane;
    auto ldrow = [&](int r, float* s) {
        const float* p = &tile[r * PITCH + base_f];
        const float4 v = *reinterpret_cast<const float4*>(p + 4);
        float lf = p[3];
        float rt = p[8];
        if (lane == 0  && !leftOK)  lf = 0.0f;   // smem[3] unwritten on bx==0
        if (lane == 31 && !rightOK) rt = 0.0f;   // smem[132] unwritten on bx==last
        s[0] = lf; s[1] = v.x; s[2] = v.y; s[3] = v.z; s[4] = v.w; s[5] = rt;
    };

    float s0[6], s1[6], s2[6];
    const int lr0 = 4 * wid;
    ldrow(lr0,     s0);
    ldrow(lr0 + 1, s1);

    float* ro = ob + (size_t)(row0 + 4 * wid) * W + colbase + base_f;

    #pragma unroll
    for (int oo = 0; oo < 4; oo++) {
        ldrow(lr0 + 2 + oo, s2);

        float a0 = 0.f, a1 = 0.f, a2 = 0.f, a3 = 0.f;
        #pragma unroll
        for (int i = 0; i < 3; i++) {
            const float* s = (i == 0) ? s0 : (i == 1) ? s1 : s2;
            const float w0 = k[3 * i], w1 = k[3 * i + 1], w2 = k[3 * i + 2];
            a0 = fmaf(w0, s[0], fmaf(w1, s[1], fmaf(w2, s[2], a0)));
            a1 = fmaf(w0, s[1], fmaf(w1, s[2], fmaf(w2, s[3], a1)));
            a2 = fmaf(w0, s[2], fmaf(w1, s[3], fmaf(w2, s[4], a2)));
            a3 = fmaf(w0, s[3], fmaf(w1, s[4], fmaf(w2, s[5], a3)));
        }
        *reinterpret_cast<float4*>(ro) = make_float4(a0, a1, a2, a3);
        ro += W;

        #pragma unroll
        for (int i = 0; i < 6; i++) { s0[i] = s1[i]; s1[i] = s2[i]; }
    }
}

extern "C" void kernel_launch(void* const* d_in, const int* in_sizes, int n_in,
                              void* d_out, int out_size)
{
    const float* x   = (const float*)d_in[0];   // (16,1,2048,2048) fp32
    const float* w   = (const float*)d_in[1];   // (1,1,3,3) fp32
    const float* den = (const float*)d_in[2];   // (1,) fp32
    float* out = (float*)d_out;

    const int B = 16, H = 2048, W = 2048;
    (void)in_sizes; (void)n_in; (void)out_size;

    dim3 grid(W / TCOLS, H / TROWS, B);   // 16 x 64 x 16 = 16384 CTAs
    dim3 block(256);
    conv3x3_bulk<<<grid, block>>>(x, w, den, out, H, W);
}

// round 7
// speedup vs baseline: 1.4024x; 1.4024x over previous
#include <cuda_runtime.h>
#include <cstdint>

// 3x3 stride-1 pad-1 conv, 1 channel, weight = w * outer(kx,kx), kx=[den,1,den].
// x: (16,1,2048,2048) fp32 -> out same shape.
// R4 cp.async fill (proven: DRAM 75%) + cross-tile double buffering:
// each CTA does the same (x,y) tile for batches b and b+8; tile B streams
// while tile A computes, eliminating the per-CTA load-idle window.

#define TCOLS 128
#define TROWS 32
#define SROWS 34             // TROWS + 2
#define PITCH 136            // 4 + 128 + 4 floats
#define NCHUNK (SROWS * 34)  // 1156 float4 chunks per tile

__global__ __launch_bounds__(256)
void conv3x3_db(const float* __restrict__ x,
                const float* __restrict__ w,
                const float* __restrict__ den,
                float* __restrict__ out,
                int H, int W)
{
    __shared__ float tile[2][SROWS * PITCH];

    const int tid  = threadIdx.x;
    const int lane = tid & 31;
    const int wid  = tid >> 5;

    const int colbase = blockIdx.x * TCOLS;
    const int row0    = blockIdx.y * TROWS;
    const int b0      = blockIdx.z;          // batches b0 and b0+8

    const size_t img = (size_t)H * W;

    // ---- fill one tile buffer for batch b (R4-proven pattern) ----
    auto fill = [&](int buf, int b) {
        const float* __restrict__ xb = x + (size_t)b * img;
        const uint32_t sbase = (uint32_t)__cvta_generic_to_shared(&tile[buf][0]);
        for (int c2 = tid; c2 < NCHUNK; c2 += 256) {
            const int r  = c2 / 34;
            const int cc = c2 - r * 34;
            const int gy = row0 - 1 + r;
            const int gx = colbase - 4 + 4 * cc;
            const bool valid = ((unsigned)gy < (unsigned)H) & ((unsigned)gx < (unsigned)W);
            const int off = valid ? (gy * W + gx) : 0;
            const int ss  = valid ? 16 : 0;
            const uint32_t dst = sbase + (uint32_t)(r * PITCH + 4 * cc) * 4u;
            asm volatile("cp.async.cg.shared.global [%0], [%1], 16, %2;"
                         :: "r"(dst), "l"(xb + off), "r"(ss));
        }
        asm volatile("cp.async.commit_group;");
    };

    fill(0, b0);
    fill(1, b0 + 8);

    // effective 3x3 weights (overlaps with loads in flight)
    const float d = den[0];
    const float kv[3] = {d, 1.0f, d};
    float k[9];
    #pragma unroll
    for (int i = 0; i < 3; i++)
        #pragma unroll
        for (int j = 0; j < 3; j++)
            k[i * 3 + j] = __ldg(&w[i * 3 + j]) * kv[i] * kv[j];

    const int base_f = 4 * lane;
    const int lr0 = 4 * wid;   // warp's first input smem row; outputs [4w,4w+4)

    // ---- compute one buffered tile and store to batch b ----
    auto compute = [&](int buf, int b) {
        float* __restrict__ ob = out + (size_t)b * img;
        const float* tb = &tile[buf][0];

        auto ldrow = [&](int r, float* s) {
            const float* p = tb + r * PITCH + base_f;
            const float4 v = *reinterpret_cast<const float4*>(p + 4);
            s[0] = p[3]; s[1] = v.x; s[2] = v.y; s[3] = v.z; s[4] = v.w; s[5] = p[8];
        };

        float s0[6], s1[6], s2[6];
        ldrow(lr0,     s0);
        ldrow(lr0 + 1, s1);

        float* ro = ob + (size_t)(row0 + lr0) * W + colbase + base_f;

        #pragma unroll
        for (int oo = 0; oo < 4; oo++) {
            ldrow(lr0 + 2 + oo, s2);

            float a0 = 0.f, a1 = 0.f, a2 = 0.f, a3 = 0.f;
            #pragma unroll
            for (int i = 0; i < 3; i++) {
                const float* s = (i == 0) ? s0 : (i == 1) ? s1 : s2;
                const float w0 = k[3 * i], w1 = k[3 * i + 1], w2 = k[3 * i + 2];
                a0 = fmaf(w0, s[0], fmaf(w1, s[1], fmaf(w2, s[2], a0)));
                a1 = fmaf(w0, s[1], fmaf(w1, s[2], fmaf(w2, s[3], a1)));
                a2 = fmaf(w0, s[2], fmaf(w1, s[3], fmaf(w2, s[4], a2)));
                a3 = fmaf(w0, s[3], fmaf(w1, s[4], fmaf(w2, s[5], a3)));
            }
            *reinterpret_cast<float4*>(ro) = make_float4(a0, a1, a2, a3);
            ro += W;

            #pragma unroll
            for (int i = 0; i < 6; i++) { s0[i] = s1[i]; s1[i] = s2[i]; }
        }
    };

    asm volatile("cp.async.wait_group 1;");   // tile A complete
    __syncthreads();
    compute(0, b0);                            // B still streaming during this

    asm volatile("cp.async.wait_group 0;");   // tile B complete
    __syncthreads();
    compute(1, b0 + 8);
}

extern "C" void kernel_launch(void* const* d_in, const int* in_sizes, int n_in,
                              void* d_out, int out_size)
{
    const float* x   = (const float*)d_in[0];   // (16,1,2048,2048) fp32
    const float* w   = (const float*)d_in[1];   // (1,1,3,3) fp32
    const float* den = (const float*)d_in[2];   // (1,) fp32
    float* out = (float*)d_out;

    const int B = 16, H = 2048, W = 2048;
    (void)in_sizes; (void)n_in; (void)out_size;

    dim3 grid(W / TCOLS, H / TROWS, B / 2);   // 16 x 64 x 8 = 8192 CTAs, 2 tiles each
    dim3 block(256);
    conv3x3_db<<<grid, block>>>(x, w, den, out, H, W);
}